// round 15
// baseline (speedup 1.0000x reference)
#include <cuda_runtime.h>
#include <cuda_fp16.h>
#include <cstdint>

// ---------------------------------------------------------------------------
// GAT 2-layer forward, GB300 (sm_103a)
// Stream A: prep_cvt -> wtilde -> score1 ----\
// Stream B: count -> scan -> scatter --------+-> aggx -> GEMM1b(bias+ELU)
//   -> GEMM2(+score2) -> agg2 -> out
// Layer 1 uses aggregate-then-transform: no h1 materialization.
// ---------------------------------------------------------------------------

#define N_NODES 10000
#define F_IN    256
#define H1      8
#define C1      128
#define HC1     1024
#define C2      128
#define E_BASE  160000
#define E_TOT   (E_BASE + N_NODES)
#define SLOPE   0.2f

__device__ __half g_xh[N_NODES * F_IN];
__device__ __half g_w1t[HC1 * F_IN];
__device__ __half g_w2t[C2 * HC1];
__device__ float  g_wt[16 * F_IN];              // [0..7]=src, [8..15]=dst
__device__ __half g_aggx[N_NODES * H1 * F_IN];  // [N][8][256]
__device__ __half g_act1h[N_NODES * HC1];
__device__ __half g_h2h[N_NODES * C2];
__device__ float  g_s1s[N_NODES * H1];
__device__ float  g_s1d[N_NODES * H1];
__device__ float  g_s2s[N_NODES];
__device__ float  g_s2d[N_NODES];
__device__ int    g_deg[N_NODES];
__device__ int    g_rows[N_NODES + 1];
__device__ int    g_cur[N_NODES];
__device__ int    g_csr[E_TOT + 16];

// ---------------------------------------------------------------------------
// prep_cvt: cvt_x | W1^T | W2^T | zero(wt, s2s, s2d)
// ---------------------------------------------------------------------------
__device__ __forceinline__ void tr_cvt_tile(const float* __restrict__ W,
                                            __half* __restrict__ Wt,
                                            int K, int N, int bx, int by,
                                            float (*t)[33]) {
    int tx = threadIdx.x & 31, ty = threadIdx.x >> 5;
#pragma unroll
    for (int i = 0; i < 4; i++) {
        int row = ty + i * 8;
        t[row][tx] = W[(size_t)(by + row) * N + bx + tx];
    }
    __syncthreads();
#pragma unroll
    for (int i = 0; i < 4; i++) {
        int row = ty + i * 8;
        Wt[(size_t)(bx + row) * K + by + tx] = __float2half_rn(t[tx][row]);
    }
}

__global__ __launch_bounds__(256)
void k_prep_cvt(const float* __restrict__ x,
                const float* __restrict__ W1, const float* __restrict__ W2) {
    __shared__ float t[32][33];
    int b = blockIdx.x;
    if (b < 625) {
        int i0 = b * 1024 + threadIdx.x;
#pragma unroll
        for (int j = 0; j < 4; j++) {
            int i = i0 + j * 256;
            float4 v = ((const float4*)x)[i];
            __half2 p0 = __floats2half2_rn(v.x, v.y);
            __half2 p1 = __floats2half2_rn(v.z, v.w);
            uint2 u;
            u.x = *(uint32_t*)&p0;
            u.y = *(uint32_t*)&p1;
            ((uint2*)g_xh)[i] = u;
        }
    } else if (b < 881) {
        int bb = b - 625;
        tr_cvt_tile(W1, g_w1t, F_IN, HC1, (bb & 31) * 32, (bb >> 5) * 32, t);
    } else if (b < 1009) {
        int bb = b - 881;
        tr_cvt_tile(W2, g_w2t, HC1, C2, (bb & 3) * 32, (bb >> 2) * 32, t);
    } else {
        int bb = b - 1009;   // 0..6
        float4 z = make_float4(0.f, 0.f, 0.f, 0.f);
        if (bb == 0) {
#pragma unroll
            for (int j = 0; j < 4; j++)
                *(float4*)&g_wt[j * 1024 + threadIdx.x * 4] = z;
        } else if (bb < 4) {
#pragma unroll
            for (int j = 0; j < 4; j++) {
                int i = (bb - 1) * 4096 + j * 1024 + threadIdx.x * 4;
                if (i < N_NODES) *(float4*)&g_s2s[i] = z;
            }
        } else {
#pragma unroll
            for (int j = 0; j < 4; j++) {
                int i = (bb - 4) * 4096 + j * 1024 + threadIdx.x * 4;
                if (i < N_NODES) *(float4*)&g_s2d[i] = z;
            }
        }
    }
}

// wtilde: g_wt[b][k] = sum_c w1t[h*128+c][k] * a[h][c]; partials over 32-c
__global__ __launch_bounds__(256)
void k_wtilde(const float* __restrict__ a_src1, const float* __restrict__ a_dst1) {
    int b = blockIdx.x;                 // 0..15
    int which = b >> 3, h = b & 7;
    const float* a = (which ? a_dst1 : a_src1) + h * C1;
    int c0 = blockIdx.y * 32;
    int k = threadIdx.x;
    float s = 0.f;
#pragma unroll
    for (int i = 0; i < 32; i++) {
        int c = c0 + i;
        s = fmaf(__half2float(g_w1t[(size_t)(h * C1 + c) * F_IN + k]), a[c], s);
    }
    atomicAdd(&g_wt[b * F_IN + k], s);
}

// score1: s1s/s1d = x @ wt; warp per node
__global__ __launch_bounds__(256)
void k_score1(void) {
    __shared__ float sw[16][F_IN];
    for (int i = threadIdx.x; i < 16 * F_IN; i += 256)
        sw[i >> 8][i & 255] = g_wt[i];
    __syncthreads();
    int node = blockIdx.x * 8 + (threadIdx.x >> 5);
    int lane = threadIdx.x & 31;
    uint4 u = *(const uint4*)(g_xh + (size_t)node * F_IN + lane * 8);
    float xv[8];
    {
        float2 f0 = __half22float2(*(__half2*)&u.x);
        float2 f1 = __half22float2(*(__half2*)&u.y);
        float2 f2 = __half22float2(*(__half2*)&u.z);
        float2 f3 = __half22float2(*(__half2*)&u.w);
        xv[0] = f0.x; xv[1] = f0.y; xv[2] = f1.x; xv[3] = f1.y;
        xv[4] = f2.x; xv[5] = f2.y; xv[6] = f3.x; xv[7] = f3.y;
    }
    float r[16];
#pragma unroll
    for (int t = 0; t < 16; t++) {
        float4 w0 = *(const float4*)&sw[t][lane * 8];
        float4 w1 = *(const float4*)&sw[t][lane * 8 + 4];
        r[t] = xv[0] * w0.x + xv[1] * w0.y + xv[2] * w0.z + xv[3] * w0.w
             + xv[4] * w1.x + xv[5] * w1.y + xv[6] * w1.z + xv[7] * w1.w;
    }
#pragma unroll
    for (int o = 16; o; o >>= 1)
#pragma unroll
        for (int t = 0; t < 16; t++)
            r[t] += __shfl_xor_sync(~0u, r[t], o);
    if (lane < 8)       g_s1s[node * H1 + lane] = r[lane];
    else if (lane < 16) g_s1d[node * H1 + (lane - 8)] = r[lane];
}

// ---------------------------------------------------------------------------
// CSR build (stream B)
// ---------------------------------------------------------------------------
__global__ void k_count(const int* __restrict__ ei, int E) {
    int i0 = (blockIdx.x * blockDim.x + threadIdx.x) * 4;
    int tot = E + N_NODES;
#pragma unroll
    for (int j = 0; j < 4; j++) {
        int i = i0 + j;
        if (i < tot) {
            int dst = (i < E) ? ei[E + i] : (i - E);
            atomicAdd(&g_deg[dst], 1);
        }
    }
}

__global__ void k_scan() {
    __shared__ int ssum[1024];
    int tid = threadIdx.x;
    const int CH = (N_NODES + 1023) >> 10;
    int base = tid * CH;
    int s = 0;
    for (int i = 0; i < CH; i++) {
        int idx = base + i;
        if (idx < N_NODES) s += g_deg[idx];
    }
    ssum[tid] = s;
    __syncthreads();
    for (int off = 1; off < 1024; off <<= 1) {
        int v = (tid >= off) ? ssum[tid - off] : 0;
        __syncthreads();
        ssum[tid] += v;
        __syncthreads();
    }
    int run = (tid == 0) ? 0 : ssum[tid - 1];
    for (int i = 0; i < CH; i++) {
        int idx = base + i;
        if (idx < N_NODES) {
            g_rows[idx] = run;
            g_cur[idx]  = run;
            run += g_deg[idx];
        }
    }
    if (tid == 1023) g_rows[N_NODES] = ssum[1023];
}

__global__ void k_scatter(const int* __restrict__ ei, int E) {
    int i0 = (blockIdx.x * blockDim.x + threadIdx.x) * 4;
    int tot = E + N_NODES;
#pragma unroll
    for (int j = 0; j < 4; j++) {
        int i = i0 + j;
        if (i < tot) {
            int src = (i < E) ? ei[i]     : (i - E);
            int dst = (i < E) ? ei[E + i] : (i - E);
            int p = atomicAdd(&g_cur[dst], 1);
            g_csr[p] = src;
        }
    }
}

// ---------------------------------------------------------------------------
// aggx: one block (128 thr) per dst node; online softmax per head;
// gather x (512B/edge), 8 head-weighted accumulators; write aggx fp16.
// ---------------------------------------------------------------------------
__global__ __launch_bounds__(128)
void k_aggx(void) {
    int n = blockIdx.x;
    int tid = threadIdx.x, wid = tid >> 5, lane = tid & 31;
    __shared__ float  sdl[8], smax[8], sden[8];
    __shared__ float2 wr[4][8];
    __shared__ float  sal[16][8];
    __shared__ int    ssrc[16];

    if (tid < 8) sdl[tid] = g_s1d[n * H1 + tid];
    int r0 = g_rows[n], r1 = g_rows[n + 1];
    int deg = r1 - r0;
    __syncthreads();

    int myh = tid & 7;
    float sdh = sdl[myh];

    float m = -3.0e38f, s = 0.f;
    for (int idx = tid; idx < deg * 8; idx += 128) {
        int src = g_csr[r0 + (idx >> 3)];
        float v = g_s1s[src * H1 + myh] + sdh;
        v = v > 0.f ? v : SLOPE * v;
        float nm = fmaxf(m, v);
        s = s * __expf(m - nm) + __expf(v - nm);
        m = nm;
    }
#pragma unroll
    for (int o = 8; o <= 16; o <<= 1) {
        float om = __shfl_xor_sync(~0u, m, o);
        float os = __shfl_xor_sync(~0u, s, o);
        float nm = fmaxf(m, om);
        s = s * __expf(m - nm) + os * __expf(om - nm);
        m = nm;
    }
    if (lane < 8) wr[wid][lane] = make_float2(m, s);
    __syncthreads();
    if (tid < 8) {
        float M = wr[0][tid].x, S = wr[0][tid].y;
#pragma unroll
        for (int w = 1; w < 4; w++) {
            float m2 = wr[w][tid].x, s2 = wr[w][tid].y;
            float nm = fmaxf(M, m2);
            S = S * __expf(M - nm) + s2 * __expf(m2 - nm);
            M = nm;
        }
        smax[tid] = M;
        sden[tid] = 1.f / S;
    }
    __syncthreads();

    float acc[8][2];
#pragma unroll
    for (int h = 0; h < 8; h++) acc[h][0] = acc[h][1] = 0.f;
    int ch = tid * 2;

    for (int e0 = r0; e0 < r1; e0 += 16) {
        int mc = min(16, r1 - e0);
        if (tid < mc * 8) {
            int e = e0 + (tid >> 3);
            int h = tid & 7;
            int src = g_csr[e];
            if (h == 0) ssrc[tid >> 3] = src;
            float v = g_s1s[src * H1 + h] + sdl[h];
            v = v > 0.f ? v : SLOPE * v;
            sal[tid >> 3][h] = __expf(v - smax[h]) * sden[h];
        }
        __syncthreads();
#pragma unroll 2
        for (int j = 0; j < mc; j++) {
            int src = ssrc[j];
            uint32_t u = *(const uint32_t*)(g_xh + (size_t)src * F_IN + ch);
            float2 f = __half22float2(*(__half2*)&u);
#pragma unroll
            for (int h = 0; h < 8; h++) {
                float a = sal[j][h];
                acc[h][0] = fmaf(f.x, a, acc[h][0]);
                acc[h][1] = fmaf(f.y, a, acc[h][1]);
            }
        }
        __syncthreads();
    }
#pragma unroll
    for (int h = 0; h < 8; h++) {
        __half2 hv = __floats2half2_rn(acc[h][0], acc[h][1]);
        *(__half2*)(g_aggx + ((size_t)n * H1 + h) * F_IN + ch) = hv;
    }
}

// ---------------------------------------------------------------------------
// fp16 MMA + cp.async + ldmatrix helpers
// ---------------------------------------------------------------------------
__device__ __forceinline__ void mma_f16(float* c, const uint32_t* a, const uint32_t* b) {
    asm volatile(
        "mma.sync.aligned.m16n8k16.row.col.f32.f16.f16.f32 "
        "{%0,%1,%2,%3}, {%4,%5,%6,%7}, {%8,%9}, {%0,%1,%2,%3};"
        : "+f"(c[0]), "+f"(c[1]), "+f"(c[2]), "+f"(c[3])
        : "r"(a[0]), "r"(a[1]), "r"(a[2]), "r"(a[3]), "r"(b[0]), "r"(b[1]));
}

__device__ __forceinline__ void cp16(uint32_t dst, const void* src, bool p) {
    int sz = p ? 16 : 0;
    asm volatile("cp.async.cg.shared.global [%0], [%1], 16, %2;"
                 :: "r"(dst), "l"(src), "r"(sz));
}
#define CP_COMMIT() asm volatile("cp.async.commit_group;")
#define CP_WAIT(n)  asm volatile("cp.async.wait_group %0;" :: "n"(n))

__device__ __forceinline__ void ldsm_x4(uint32_t& r0, uint32_t& r1,
                                        uint32_t& r2, uint32_t& r3, uint32_t a) {
    asm volatile("ldmatrix.sync.aligned.m8n8.x4.shared.b16 {%0,%1,%2,%3}, [%4];"
                 : "=r"(r0), "=r"(r1), "=r"(r2), "=r"(r3) : "r"(a));
}
__device__ __forceinline__ void ldsm_x2(uint32_t& r0, uint32_t& r1, uint32_t a) {
    asm volatile("ldmatrix.sync.aligned.m8n8.x2.shared.b16 {%0,%1}, [%2];"
                 : "=r"(r0), "=r"(r1) : "r"(a));
}

// ---------------------------------------------------------------------------
// GEMM: C[M,Ng] = A'[M,K] @ Bt[Ng,K]^T, fp16 in/out, fp32 accum.
// A' rows have stride lda; A base shifts by aoff per 128 output cols.
// MODE 0: fp16 store + fused score epilogue (atomicAdd into ss/sd).
// MODE 1: bias(ext) + ELU, fp16 store only.
// ---------------------------------------------------------------------------
template<int BM, int BN, int WARPS_M, int WARPS_N, int STAGES, int MODE>
__global__ __launch_bounds__(32 * WARPS_M * WARPS_N)
void k_hgemm(int M, int Ng, int K,
             const __half* __restrict__ A, int lda, int aoff,
             const __half* __restrict__ Bt,
             __half* __restrict__ Ch,
             float* __restrict__ ss, float* __restrict__ sd,
             const float* __restrict__ a_src, const float* __restrict__ a_dst,
             int HS) {
    constexpr int BK = 32;
    constexpr int SA = BK + 8;
    constexpr int NTHR = 32 * WARPS_M * WARPS_N;
    constexpr int WM = BM / WARPS_M, WN = BN / WARPS_N;
    constexpr int MT = WM / 16, NT = WN / 8;
    constexpr int RPR = NTHR / 4;
    constexpr int AROUND = BM / RPR, BROUND = BN / RPR;

    extern __shared__ __align__(16) char smem_raw[];
    __half* AsBase = (__half*)smem_raw;
    __half* BsBase = AsBase + STAGES * BM * SA;
    float* s_red = (float*)(BsBase + STAGES * BN * SA);

    int tid = threadIdx.x, wid = tid >> 5, lane = tid & 31;
    int bm0 = blockIdx.y * BM, bn0 = blockIdx.x * BN;
    int wm_idx = wid / WARPS_N, wn_idx = wid % WARPS_N;
    int wm = wm_idx * WM, wn = wn_idx * WN;
    int head = (bn0 >> 7);
    const __half* Ab = A + (size_t)head * aoff;

    float acc[MT][NT][4];
#pragma unroll
    for (int i = 0; i < MT; i++)
#pragma unroll
        for (int j = 0; j < NT; j++)
#pragma unroll
            for (int l = 0; l < 4; l++) acc[i][j][l] = 0.f;

    int ld_row = tid >> 2;
    int ld_ch  = (tid & 3) * 8;

    uint32_t as_sh = (uint32_t)__cvta_generic_to_shared(AsBase);
    uint32_t bs_sh = (uint32_t)__cvta_generic_to_shared(BsBase);
    int a_lrow = wm + (lane & 15);
    int a_lcol = (lane & 16) ? 8 : 0;
    int b_lrow = wn + (lane & 7);
    int b_lcol = (lane & 8) ? 8 : 0;

    auto cp_tile = [&](int buf, int k0) {
        __half* As = AsBase + buf * BM * SA;
        __half* Bs = BsBase + buf * BN * SA;
#pragma unroll
        for (int i = 0; i < AROUND; i++) {
            int rl = ld_row + i * RPR;
            int gr = bm0 + rl;
            uint32_t dst = (uint32_t)__cvta_generic_to_shared(&As[rl * SA + ld_ch]);
            cp16(dst, Ab + (size_t)gr * lda + k0 + ld_ch, gr < M);
        }
#pragma unroll
        for (int i = 0; i < BROUND; i++) {
            int nl = ld_row + i * RPR;
            uint32_t dst = (uint32_t)__cvta_generic_to_shared(&Bs[nl * SA + ld_ch]);
            cp16(dst, Bt + (size_t)(bn0 + nl) * K + k0 + ld_ch, true);
        }
        CP_COMMIT();
    };

    auto compute = [&](int buf) {
        uint32_t as0 = as_sh + (uint32_t)(buf * BM * SA) * 2;
        uint32_t bs0 = bs_sh + (uint32_t)(buf * BN * SA) * 2;
#pragma unroll
        for (int ks = 0; ks < 2; ks++) {
            uint32_t af[MT][4], bf[NT][2];
#pragma unroll
            for (int mt = 0; mt < MT; mt++) {
                uint32_t addr = as0 + ((a_lrow + mt * 16) * SA + ks * 16 + a_lcol) * 2;
                ldsm_x4(af[mt][0], af[mt][1], af[mt][2], af[mt][3], addr);
            }
#pragma unroll
            for (int nt = 0; nt < NT; nt++) {
                uint32_t addr = bs0 + ((b_lrow + nt * 8) * SA + ks * 16 + b_lcol) * 2;
                ldsm_x2(bf[nt][0], bf[nt][1], addr);
            }
#pragma unroll
            for (int mt = 0; mt < MT; mt++)
#pragma unroll
                for (int nt = 0; nt < NT; nt++)
                    mma_f16(acc[mt][nt], af[mt], bf[nt]);
        }
    };

    int iters = K / BK;
    for (int s = 0; s < STAGES - 1 && s < iters; s++) cp_tile(s, s * BK);
    for (int it = 0; it < iters; it++) {
        int rem = iters - 1 - it;
        if (rem >= STAGES - 2) { CP_WAIT(STAGES - 2); }
        else if (STAGES > 3 && rem == 1) { CP_WAIT(1); }
        else { CP_WAIT(0); }
        __syncthreads();
        compute(it % STAGES);
        if (it + STAGES - 1 < iters)
            cp_tile((it + STAGES - 1) % STAGES, (it + STAGES - 1) * BK);
    }

    if (MODE == 1) {
        // bias + ELU epilogue
#pragma unroll
        for (int nt = 0; nt < NT; nt++) {
            int cl = wn + nt * 8 + (lane & 3) * 2;
            float b0v = a_src[bn0 + cl], b1v = a_src[bn0 + cl + 1];
#pragma unroll
            for (int mt = 0; mt < MT; mt++) {
                int r = bm0 + wm + mt * 16 + (lane >> 2);
                int c = bn0 + cl;
                float t0 = acc[mt][nt][0] + b0v, t1 = acc[mt][nt][1] + b1v;
                float t2 = acc[mt][nt][2] + b0v, t3 = acc[mt][nt][3] + b1v;
                t0 = t0 > 0.f ? t0 : expm1f(t0);
                t1 = t1 > 0.f ? t1 : expm1f(t1);
                t2 = t2 > 0.f ? t2 : expm1f(t2);
                t3 = t3 > 0.f ? t3 : expm1f(t3);
                if (r < M)
                    *(__half2*)(Ch + (size_t)r * Ng + c) = __floats2half2_rn(t0, t1);
                if (r + 8 < M)
                    *(__half2*)(Ch + (size_t)(r + 8) * Ng + c) = __floats2half2_rn(t2, t3);
            }
        }
        return;
    }

    // MODE 0: fp16 store + fused score partials
    float ps[MT][2], pd[MT][2];
#pragma unroll
    for (int mt = 0; mt < MT; mt++) {
        ps[mt][0] = ps[mt][1] = 0.f;
        pd[mt][0] = pd[mt][1] = 0.f;
    }
#pragma unroll
    for (int nt = 0; nt < NT; nt++) {
        int cl = wn + nt * 8 + (lane & 3) * 2;
        float a0s = a_src[bn0 + cl], a1s = a_src[bn0 + cl + 1];
        float a0d = a_dst[bn0 + cl], a1d = a_dst[bn0 + cl + 1];
#pragma unroll
        for (int mt = 0; mt < MT; mt++) {
            int r = bm0 + wm + mt * 16 + (lane >> 2);
            int c = bn0 + cl;
            if (r < M)
                *(__half2*)(Ch + (size_t)r * Ng + c) =
                    __floats2half2_rn(acc[mt][nt][0], acc[mt][nt][1]);
            if (r + 8 < M)
                *(__half2*)(Ch + (size_t)(r + 8) * Ng + c) =
                    __floats2half2_rn(acc[mt][nt][2], acc[mt][nt][3]);
            ps[mt][0] = fmaf(acc[mt][nt][0], a0s, fmaf(acc[mt][nt][1], a1s, ps[mt][0]));
            ps[mt][1] = fmaf(acc[mt][nt][2], a0s, fmaf(acc[mt][nt][3], a1s, ps[mt][1]));
            pd[mt][0] = fmaf(acc[mt][nt][0], a0d, fmaf(acc[mt][nt][1], a1d, pd[mt][0]));
            pd[mt][1] = fmaf(acc[mt][nt][2], a0d, fmaf(acc[mt][nt][3], a1d, pd[mt][1]));
        }
    }
#pragma unroll
    for (int o = 1; o <= 2; o <<= 1) {
#pragma unroll
        for (int mt = 0; mt < MT; mt++) {
            ps[mt][0] += __shfl_xor_sync(~0u, ps[mt][0], o);
            ps[mt][1] += __shfl_xor_sync(~0u, ps[mt][1], o);
            pd[mt][0] += __shfl_xor_sync(~0u, pd[mt][0], o);
            pd[mt][1] += __shfl_xor_sync(~0u, pd[mt][1], o);
        }
    }
    if ((lane & 3) == 0) {
#pragma unroll
        for (int mt = 0; mt < MT; mt++) {
            int row = wm + mt * 16 + (lane >> 2);
            s_red[(row * WARPS_N + wn_idx) * 2 + 0] = ps[mt][0];
            s_red[(row * WARPS_N + wn_idx) * 2 + 1] = pd[mt][0];
            s_red[((row + 8) * WARPS_N + wn_idx) * 2 + 0] = ps[mt][1];
            s_red[((row + 8) * WARPS_N + wn_idx) * 2 + 1] = pd[mt][1];
        }
    }
    __syncthreads();
    if (tid < BM) {
        int r = bm0 + tid;
        if (r < M) {
            float s = 0.f, d = 0.f;
#pragma unroll
            for (int w = 0; w < WARPS_N; w++) {
                s += s_red[(tid * WARPS_N + w) * 2 + 0];
                d += s_red[(tid * WARPS_N + w) * 2 + 1];
            }
            atomicAdd(&ss[(size_t)r * HS + head], s);
            atomicAdd(&sd[(size_t)r * HS + head], d);
        }
    }
}

// ---------------------------------------------------------------------------
// agg2: fp16 gather; writes final fp32 output
// ---------------------------------------------------------------------------
__global__ __launch_bounds__(128)
void k_agg2(const float* __restrict__ b2, float* __restrict__ out) {
    int n = blockIdx.x;
    int tid = threadIdx.x, wid = tid >> 5, lane = tid & 31;
    __shared__ float s_sd, s_m, s_d;
    __shared__ float2 wr[4];
    __shared__ float sal[64];
    __shared__ int   ssrc[64];

    if (tid == 0) s_sd = g_s2d[n];
    int r0 = g_rows[n], r1 = g_rows[n + 1];
    int deg = r1 - r0;
    __syncthreads();
    float sdv = s_sd;

    float m = -3.0e38f, s = 0.f;
    for (int i = tid; i < deg; i += 128) {
        int src = g_csr[r0 + i];
        float v = g_s2s[src] + sdv;
        v = v > 0.f ? v : SLOPE * v;
        float nm = fmaxf(m, v);
        s = s * __expf(m - nm) + __expf(v - nm);
        m = nm;
    }
#pragma unroll
    for (int o = 16; o; o >>= 1) {
        float om = __shfl_xor_sync(~0u, m, o);
        float os = __shfl_xor_sync(~0u, s, o);
        float nm = fmaxf(m, om);
        s = s * __expf(m - nm) + os * __expf(om - nm);
        m = nm;
    }
    if (!lane) wr[wid] = make_float2(m, s);
    __syncthreads();
    if (tid == 0) {
        float M = wr[0].x, S = wr[0].y;
#pragma unroll
        for (int w = 1; w < 4; w++) {
            float m2 = wr[w].x, s2 = wr[w].y;
            float nm = fmaxf(M, m2);
            S = S * __expf(M - nm) + s2 * __expf(m2 - nm);
            M = nm;
        }
        s_m = M;
        s_d = 1.f / S;
    }
    __syncthreads();
    float M = s_m, inv = s_d;

    float acc = 0.f;
    for (int e0 = r0; e0 < r1; e0 += 64) {
        int mc = min(64, r1 - e0);
        if (tid < mc) {
            int src = g_csr[e0 + tid];
            float v = g_s2s[src] + sdv;
            v = v > 0.f ? v : SLOPE * v;
            sal[tid] = __expf(v - M) * inv;
            ssrc[tid] = src;
        }
        __syncthreads();
#pragma unroll 4
        for (int j = 0; j < mc; j++) {
            float hv = __half2float(g_h2h[(size_t)ssrc[j] * C2 + tid]);
            acc = fmaf(hv, sal[j], acc);
        }
        __syncthreads();
    }
    out[(size_t)n * C2 + tid] = acc + b2[tid];
}

// ---------------------------------------------------------------------------
// launch
// ---------------------------------------------------------------------------
extern "C" void kernel_launch(void* const* d_in, const int* in_sizes, int n_in,
                              void* d_out, int out_size) {
    const float* x      = (const float*)d_in[0];
    const int*   ei     = (const int*)  d_in[1];
    const float* W1     = (const float*)d_in[2];
    const float* a_src1 = (const float*)d_in[3];
    const float* a_dst1 = (const float*)d_in[4];
    const float* b1     = (const float*)d_in[5];
    const float* W2     = (const float*)d_in[6];
    const float* a_src2 = (const float*)d_in[7];
    const float* a_dst2 = (const float*)d_in[8];
    const float* b2     = (const float*)d_in[9];
    float* out = (float*)d_out;

    int E = in_sizes[1] / 2;
    int tot = E + N_NODES;

    __half *p_aggx, *p_w1t, *p_w2t, *p_act1h, *p_h2h;
    float *p_s2s, *p_s2d;
    int* p_deg;
    cudaGetSymbolAddress((void**)&p_aggx,  g_aggx);
    cudaGetSymbolAddress((void**)&p_w1t,   g_w1t);
    cudaGetSymbolAddress((void**)&p_w2t,   g_w2t);
    cudaGetSymbolAddress((void**)&p_act1h, g_act1h);
    cudaGetSymbolAddress((void**)&p_h2h,   g_h2h);
    cudaGetSymbolAddress((void**)&p_s2s,   g_s2s);
    cudaGetSymbolAddress((void**)&p_s2d,   g_s2d);
    cudaGetSymbolAddress((void**)&p_deg,   g_deg);

    const int SMEM1 = 3 * (128 + 128) * 40 * 2 + 128 * 2 * 2 * 4;   // 63488
    const int SMEM2 = 4 * (64 + 64) * 40 * 2 + 64 * 2 * 2 * 4;      // 41984

    static cudaStream_t sB = nullptr;
    static cudaEvent_t evFork = nullptr, evJoin = nullptr;
    if (!sB) {
        cudaStreamCreateWithFlags(&sB, cudaStreamNonBlocking);
        cudaEventCreateWithFlags(&evFork, cudaEventDisableTiming);
        cudaEventCreateWithFlags(&evJoin, cudaEventDisableTiming);
        cudaFuncSetAttribute(k_hgemm<128, 128, 2, 2, 3, 1>,
                             cudaFuncAttributeMaxDynamicSharedMemorySize, SMEM1);
        cudaFuncSetAttribute(k_hgemm<64, 64, 2, 2, 4, 0>,
                             cudaFuncAttributeMaxDynamicSharedMemorySize, SMEM2);
    }

    int cb = (tot + 1023) / 1024;

    // fork: CSR chain on stream B
    cudaEventRecord(evFork, 0);
    cudaStreamWaitEvent(sB, evFork, 0);
    cudaMemsetAsync(p_deg, 0, N_NODES * sizeof(int), sB);
    k_count<<<cb, 256, 0, sB>>>(ei, E);
    k_scan<<<1, 1024, 0, sB>>>();
    k_scatter<<<cb, 256, 0, sB>>>(ei, E);
    cudaEventRecord(evJoin, sB);

    // stream A: convert + wtilde + score1
    k_prep_cvt<<<1016, 256>>>(x, W1, W2);
    k_wtilde<<<dim3(16, 4), 256>>>(a_src1, a_dst1);
    k_score1<<<N_NODES / 8, 256>>>();

    // join: aggx needs CSR + scores
    cudaStreamWaitEvent(0, evJoin, 0);
    k_aggx<<<N_NODES, 128>>>();

    // GEMM1b: aggx @ W1 per head, bias+ELU -> act1h
    k_hgemm<128, 128, 2, 2, 3, 1><<<dim3(HC1 / 128, (N_NODES + 127) / 128), 128, SMEM1>>>(
        N_NODES, HC1, F_IN, p_aggx, H1 * F_IN, F_IN, p_w1t, p_act1h,
        nullptr, nullptr, b1, nullptr, H1);

    // Layer 2: GEMM2 (+fused score2) -> agg2
    k_hgemm<64, 64, 2, 2, 4, 0><<<dim3(C2 / 64, (N_NODES + 63) / 64), 128, SMEM2>>>(
        N_NODES, C2, HC1, p_act1h, HC1, 0, p_w2t, p_h2h,
        p_s2s, p_s2d, a_src2, a_dst2, 1);
    k_agg2<<<N_NODES, 128>>>(b2, out);
}

// round 16
// speedup vs baseline: 1.3723x; 1.3723x over previous
#include <cuda_runtime.h>
#include <cuda_fp16.h>
#include <cstdint>

// ---------------------------------------------------------------------------
// GAT 2-layer forward, GB300 (sm_103a)
// Stream A: prep_cvt(x,W1,zero s1) -> GEMM1(+score1) --\
// Stream B: prep2(W2,zero s2) | count->scan->scatter --+-> agg1 -> GEMM2 -> agg2
// ---------------------------------------------------------------------------

#define N_NODES 10000
#define F_IN    256
#define H1      8
#define C1      128
#define HC1     1024
#define C2      128
#define E_BASE  160000
#define E_TOT   (E_BASE + N_NODES)
#define SLOPE   0.2f

__device__ __half g_xh[N_NODES * F_IN];
__device__ __half g_w1t[HC1 * F_IN];
__device__ __half g_w2t[C2 * HC1];
__device__ __half g_h1h[N_NODES * HC1];
__device__ __half g_act1h[N_NODES * HC1];
__device__ __half g_h2h[N_NODES * C2];
__device__ float  g_s1s[N_NODES * H1];
__device__ float  g_s1d[N_NODES * H1];
__device__ float  g_s2s[N_NODES];
__device__ float  g_s2d[N_NODES];
__device__ int    g_deg[N_NODES];
__device__ int    g_rows[N_NODES + 1];
__device__ int    g_cur[N_NODES];
__device__ int    g_csr[E_TOT + 16];

// ---------------------------------------------------------------------------
// prep kernels
// ---------------------------------------------------------------------------
__device__ __forceinline__ void tr_cvt_tile(const float* __restrict__ W,
                                            __half* __restrict__ Wt,
                                            int K, int N, int bx, int by,
                                            float (*t)[33]) {
    int tx = threadIdx.x & 31, ty = threadIdx.x >> 5;
#pragma unroll
    for (int i = 0; i < 4; i++) {
        int row = ty + i * 8;
        t[row][tx] = W[(size_t)(by + row) * N + bx + tx];
    }
    __syncthreads();
#pragma unroll
    for (int i = 0; i < 4; i++) {
        int row = ty + i * 8;
        Wt[(size_t)(bx + row) * K + by + tx] = __float2half_rn(t[tx][row]);
    }
}

// stream A: cvt_x | W1^T | zero s1s/s1d      (921 blocks)
__global__ __launch_bounds__(256)
void k_prep_cvt(const float* __restrict__ x, const float* __restrict__ W1) {
    __shared__ float t[32][33];
    int b = blockIdx.x;
    if (b < 625) {
        int i0 = b * 1024 + threadIdx.x;
#pragma unroll
        for (int j = 0; j < 4; j++) {
            int i = i0 + j * 256;
            float4 v = ((const float4*)x)[i];
            __half2 p0 = __floats2half2_rn(v.x, v.y);
            __half2 p1 = __floats2half2_rn(v.z, v.w);
            uint2 u;
            u.x = *(uint32_t*)&p0;
            u.y = *(uint32_t*)&p1;
            ((uint2*)g_xh)[i] = u;
        }
    } else if (b < 881) {
        int bb = b - 625;
        tr_cvt_tile(W1, g_w1t, F_IN, HC1, (bb & 31) * 32, (bb >> 5) * 32, t);
    } else {
        int bb = b - 881;   // 0..39
        float4 z = make_float4(0.f, 0.f, 0.f, 0.f);
        if (bb < 20) {
#pragma unroll
            for (int j = 0; j < 4; j++) {
                int i = bb * 4096 + j * 1024 + threadIdx.x * 4;
                if (i < N_NODES * H1) *(float4*)&g_s1s[i] = z;
            }
        } else {
#pragma unroll
            for (int j = 0; j < 4; j++) {
                int i = (bb - 20) * 4096 + j * 1024 + threadIdx.x * 4;
                if (i < N_NODES * H1) *(float4*)&g_s1d[i] = z;
            }
        }
    }
}

// stream B: W2^T | zero s2s/s2d    (134 blocks)
__global__ __launch_bounds__(256)
void k_prep2(const float* __restrict__ W2) {
    __shared__ float t[32][33];
    int b = blockIdx.x;
    if (b < 128) {
        tr_cvt_tile(W2, g_w2t, HC1, C2, (b & 3) * 32, (b >> 2) * 32, t);
    } else {
        int bb = b - 128;   // 0..5
        float4 z = make_float4(0.f, 0.f, 0.f, 0.f);
        if (bb < 3) {
#pragma unroll
            for (int j = 0; j < 4; j++) {
                int i = bb * 4096 + j * 1024 + threadIdx.x * 4;
                if (i < N_NODES) *(float4*)&g_s2s[i] = z;
            }
        } else {
#pragma unroll
            for (int j = 0; j < 4; j++) {
                int i = (bb - 3) * 4096 + j * 1024 + threadIdx.x * 4;
                if (i < N_NODES) *(float4*)&g_s2d[i] = z;
            }
        }
    }
}

// ---------------------------------------------------------------------------
// CSR build (stream B)
// ---------------------------------------------------------------------------
__global__ void k_count(const int* __restrict__ ei, int E) {
    int i0 = (blockIdx.x * blockDim.x + threadIdx.x) * 4;
    int tot = E + N_NODES;
#pragma unroll
    for (int j = 0; j < 4; j++) {
        int i = i0 + j;
        if (i < tot) {
            int dst = (i < E) ? ei[E + i] : (i - E);
            atomicAdd(&g_deg[dst], 1);
        }
    }
}

__global__ void k_scan() {
    __shared__ int ssum[1024];
    int tid = threadIdx.x;
    const int CH = (N_NODES + 1023) >> 10;
    int base = tid * CH;
    int s = 0;
    for (int i = 0; i < CH; i++) {
        int idx = base + i;
        if (idx < N_NODES) s += g_deg[idx];
    }
    ssum[tid] = s;
    __syncthreads();
    for (int off = 1; off < 1024; off <<= 1) {
        int v = (tid >= off) ? ssum[tid - off] : 0;
        __syncthreads();
        ssum[tid] += v;
        __syncthreads();
    }
    int run = (tid == 0) ? 0 : ssum[tid - 1];
    for (int i = 0; i < CH; i++) {
        int idx = base + i;
        if (idx < N_NODES) {
            g_rows[idx] = run;
            g_cur[idx]  = run;
            run += g_deg[idx];
        }
    }
    if (tid == 1023) g_rows[N_NODES] = ssum[1023];
}

__global__ void k_scatter(const int* __restrict__ ei, int E) {
    int i0 = (blockIdx.x * blockDim.x + threadIdx.x) * 4;
    int tot = E + N_NODES;
#pragma unroll
    for (int j = 0; j < 4; j++) {
        int i = i0 + j;
        if (i < tot) {
            int src = (i < E) ? ei[i]     : (i - E);
            int dst = (i < E) ? ei[E + i] : (i - E);
            int p = atomicAdd(&g_cur[dst], 1);
            g_csr[p] = src;
        }
    }
}

// ---------------------------------------------------------------------------
// fp16 MMA + cp.async + ldmatrix helpers
// ---------------------------------------------------------------------------
__device__ __forceinline__ void mma_f16(float* c, const uint32_t* a, const uint32_t* b) {
    asm volatile(
        "mma.sync.aligned.m16n8k16.row.col.f32.f16.f16.f32 "
        "{%0,%1,%2,%3}, {%4,%5,%6,%7}, {%8,%9}, {%0,%1,%2,%3};"
        : "+f"(c[0]), "+f"(c[1]), "+f"(c[2]), "+f"(c[3])
        : "r"(a[0]), "r"(a[1]), "r"(a[2]), "r"(a[3]), "r"(b[0]), "r"(b[1]));
}

__device__ __forceinline__ void cp16(uint32_t dst, const void* src, bool p) {
    int sz = p ? 16 : 0;
    asm volatile("cp.async.cg.shared.global [%0], [%1], 16, %2;"
                 :: "r"(dst), "l"(src), "r"(sz));
}
#define CP_COMMIT() asm volatile("cp.async.commit_group;")
#define CP_WAIT(n)  asm volatile("cp.async.wait_group %0;" :: "n"(n))

__device__ __forceinline__ void ldsm_x4(uint32_t& r0, uint32_t& r1,
                                        uint32_t& r2, uint32_t& r3, uint32_t a) {
    asm volatile("ldmatrix.sync.aligned.m8n8.x4.shared.b16 {%0,%1,%2,%3}, [%4];"
                 : "=r"(r0), "=r"(r1), "=r"(r2), "=r"(r3) : "r"(a));
}
__device__ __forceinline__ void ldsm_x2(uint32_t& r0, uint32_t& r1, uint32_t a) {
    asm volatile("ldmatrix.sync.aligned.m8n8.x2.shared.b16 {%0,%1}, [%2];"
                 : "=r"(r0), "=r"(r1) : "r"(a));
}

// ---------------------------------------------------------------------------
// GEMM: C[M,Ng] = A[M,K] @ Bt[Ng,K]^T, fp16 in/out, fp32 accum.
// STAGES-deep cp.async pipeline, one __syncthreads per BK-iter, ldmatrix.
// Fused attention-score epilogue via fp32 atomicAdd (ss/sd zero-initialized).
// ---------------------------------------------------------------------------
template<int BM, int BN, int WARPS_M, int WARPS_N, int STAGES>
__global__ __launch_bounds__(32 * WARPS_M * WARPS_N)
void k_hgemm(int M, int Ng, int K,
             const __half* __restrict__ A, const __half* __restrict__ Bt,
             __half* __restrict__ Ch,
             float* __restrict__ ss, float* __restrict__ sd,
             const float* __restrict__ a_src, const float* __restrict__ a_dst,
             int HS) {
    constexpr int BK = 32;
    constexpr int SA = BK + 8;
    constexpr int NTHR = 32 * WARPS_M * WARPS_N;
    constexpr int WM = BM / WARPS_M, WN = BN / WARPS_N;
    constexpr int MT = WM / 16, NT = WN / 8;
    constexpr int RPR = NTHR / 4;
    constexpr int AROUND = BM / RPR, BROUND = BN / RPR;

    extern __shared__ __align__(16) char smem_raw[];
    __half* AsBase = (__half*)smem_raw;
    __half* BsBase = AsBase + STAGES * BM * SA;
    float* s_red = (float*)(BsBase + STAGES * BN * SA);

    int tid = threadIdx.x, wid = tid >> 5, lane = tid & 31;
    int bm0 = blockIdx.y * BM, bn0 = blockIdx.x * BN;
    int wm_idx = wid / WARPS_N, wn_idx = wid % WARPS_N;
    int wm = wm_idx * WM, wn = wn_idx * WN;
    int head = (bn0 >> 7);

    float acc[MT][NT][4];
#pragma unroll
    for (int i = 0; i < MT; i++)
#pragma unroll
        for (int j = 0; j < NT; j++)
#pragma unroll
            for (int l = 0; l < 4; l++) acc[i][j][l] = 0.f;

    int ld_row = tid >> 2;
    int ld_ch  = (tid & 3) * 8;

    uint32_t as_sh = (uint32_t)__cvta_generic_to_shared(AsBase);
    uint32_t bs_sh = (uint32_t)__cvta_generic_to_shared(BsBase);
    int a_lrow = wm + (lane & 15);
    int a_lcol = (lane & 16) ? 8 : 0;
    int b_lrow = wn + (lane & 7);
    int b_lcol = (lane & 8) ? 8 : 0;

    auto cp_tile = [&](int buf, int k0) {
        __half* As = AsBase + buf * BM * SA;
        __half* Bs = BsBase + buf * BN * SA;
#pragma unroll
        for (int i = 0; i < AROUND; i++) {
            int rl = ld_row + i * RPR;
            int gr = bm0 + rl;
            uint32_t dst = (uint32_t)__cvta_generic_to_shared(&As[rl * SA + ld_ch]);
            cp16(dst, A + (size_t)gr * K + k0 + ld_ch, gr < M);
        }
#pragma unroll
        for (int i = 0; i < BROUND; i++) {
            int nl = ld_row + i * RPR;
            uint32_t dst = (uint32_t)__cvta_generic_to_shared(&Bs[nl * SA + ld_ch]);
            cp16(dst, Bt + (size_t)(bn0 + nl) * K + k0 + ld_ch, true);
        }
        CP_COMMIT();
    };

    auto compute = [&](int buf) {
        uint32_t as0 = as_sh + (uint32_t)(buf * BM * SA) * 2;
        uint32_t bs0 = bs_sh + (uint32_t)(buf * BN * SA) * 2;
#pragma unroll
        for (int ks = 0; ks < 2; ks++) {
            uint32_t af[MT][4], bf[NT][2];
#pragma unroll
            for (int mt = 0; mt < MT; mt++) {
                uint32_t addr = as0 + ((a_lrow + mt * 16) * SA + ks * 16 + a_lcol) * 2;
                ldsm_x4(af[mt][0], af[mt][1], af[mt][2], af[mt][3], addr);
            }
#pragma unroll
            for (int nt = 0; nt < NT; nt++) {
                uint32_t addr = bs0 + ((b_lrow + nt * 8) * SA + ks * 16 + b_lcol) * 2;
                ldsm_x2(bf[nt][0], bf[nt][1], addr);
            }
#pragma unroll
            for (int mt = 0; mt < MT; mt++)
#pragma unroll
                for (int nt = 0; nt < NT; nt++)
                    mma_f16(acc[mt][nt], af[mt], bf[nt]);
        }
    };

    int iters = K / BK;
    for (int s = 0; s < STAGES - 1 && s < iters; s++) cp_tile(s, s * BK);
    for (int it = 0; it < iters; it++) {
        int rem = iters - 1 - it;
        if (rem >= STAGES - 2) { CP_WAIT(STAGES - 2); }
        else if (STAGES > 3 && rem == 1) { CP_WAIT(1); }
        else { CP_WAIT(0); }
        __syncthreads();
        compute(it % STAGES);
        if (it + STAGES - 1 < iters)
            cp_tile((it + STAGES - 1) % STAGES, (it + STAGES - 1) * BK);
    }

    // ---- epilogue: fp16 store + fused score partials ----
    float ps[MT][2], pd[MT][2];
#pragma unroll
    for (int mt = 0; mt < MT; mt++) {
        ps[mt][0] = ps[mt][1] = 0.f;
        pd[mt][0] = pd[mt][1] = 0.f;
    }
#pragma unroll
    for (int nt = 0; nt < NT; nt++) {
        int cl = wn + nt * 8 + (lane & 3) * 2;
        float a0s = a_src[bn0 + cl], a1s = a_src[bn0 + cl + 1];
        float a0d = a_dst[bn0 + cl], a1d = a_dst[bn0 + cl + 1];
#pragma unroll
        for (int mt = 0; mt < MT; mt++) {
            int r = bm0 + wm + mt * 16 + (lane >> 2);
            int c = bn0 + cl;
            if (r < M)
                *(__half2*)(Ch + (size_t)r * Ng + c) =
                    __floats2half2_rn(acc[mt][nt][0], acc[mt][nt][1]);
            if (r + 8 < M)
                *(__half2*)(Ch + (size_t)(r + 8) * Ng + c) =
                    __floats2half2_rn(acc[mt][nt][2], acc[mt][nt][3]);
            ps[mt][0] = fmaf(acc[mt][nt][0], a0s, fmaf(acc[mt][nt][1], a1s, ps[mt][0]));
            ps[mt][1] = fmaf(acc[mt][nt][2], a0s, fmaf(acc[mt][nt][3], a1s, ps[mt][1]));
            pd[mt][0] = fmaf(acc[mt][nt][0], a0d, fmaf(acc[mt][nt][1], a1d, pd[mt][0]));
            pd[mt][1] = fmaf(acc[mt][nt][2], a0d, fmaf(acc[mt][nt][3], a1d, pd[mt][1]));
        }
    }
#pragma unroll
    for (int o = 1; o <= 2; o <<= 1) {
#pragma unroll
        for (int mt = 0; mt < MT; mt++) {
            ps[mt][0] += __shfl_xor_sync(~0u, ps[mt][0], o);
            ps[mt][1] += __shfl_xor_sync(~0u, ps[mt][1], o);
            pd[mt][0] += __shfl_xor_sync(~0u, pd[mt][0], o);
            pd[mt][1] += __shfl_xor_sync(~0u, pd[mt][1], o);
        }
    }
    if ((lane & 3) == 0) {
#pragma unroll
        for (int mt = 0; mt < MT; mt++) {
            int row = wm + mt * 16 + (lane >> 2);
            s_red[(row * WARPS_N + wn_idx) * 2 + 0] = ps[mt][0];
            s_red[(row * WARPS_N + wn_idx) * 2 + 1] = pd[mt][0];
            s_red[((row + 8) * WARPS_N + wn_idx) * 2 + 0] = ps[mt][1];
            s_red[((row + 8) * WARPS_N + wn_idx) * 2 + 1] = pd[mt][1];
        }
    }
    __syncthreads();
    if (tid < BM) {
        int r = bm0 + tid;
        if (r < M) {
            float s = 0.f, d = 0.f;
#pragma unroll
            for (int w = 0; w < WARPS_N; w++) {
                s += s_red[(tid * WARPS_N + w) * 2 + 0];
                d += s_red[(tid * WARPS_N + w) * 2 + 1];
            }
            atomicAdd(&ss[(size_t)r * HS + head], s);
            atomicAdd(&sd[(size_t)r * HS + head], d);
        }
    }
}

// ---------------------------------------------------------------------------
// agg1: one block (128 thr) per dst node; online softmax; fp16 gather;
// writes fp16 act1 (+b1, ELU).
// ---------------------------------------------------------------------------
__global__ __launch_bounds__(128)
void k_agg1(const float* __restrict__ b1) {
    int n = blockIdx.x;
    int tid = threadIdx.x, wid = tid >> 5, lane = tid & 31;
    __shared__ float  sdl[8], smax[8], sden[8];
    __shared__ float2 wr[4][8];
    __shared__ float  sal[16][8];
    __shared__ int    ssrc[16];

    if (tid < 8) sdl[tid] = g_s1d[n * H1 + tid];
    int r0 = g_rows[n], r1 = g_rows[n + 1];
    int deg = r1 - r0;
    __syncthreads();

    int myh = tid & 7;
    float sdh = sdl[myh];

    float m = -3.0e38f, s = 0.f;
    for (int idx = tid; idx < deg * 8; idx += 128) {
        int src = g_csr[r0 + (idx >> 3)];
        float v = g_s1s[src * H1 + myh] + sdh;
        v = v > 0.f ? v : SLOPE * v;
        float nm = fmaxf(m, v);
        s = s * __expf(m - nm) + __expf(v - nm);
        m = nm;
    }
#pragma unroll
    for (int o = 8; o <= 16; o <<= 1) {
        float om = __shfl_xor_sync(~0u, m, o);
        float os = __shfl_xor_sync(~0u, s, o);
        float nm = fmaxf(m, om);
        s = s * __expf(m - nm) + os * __expf(om - nm);
        m = nm;
    }
    if (lane < 8) wr[wid][lane] = make_float2(m, s);
    __syncthreads();
    if (tid < 8) {
        float M = wr[0][tid].x, S = wr[0][tid].y;
#pragma unroll
        for (int w = 1; w < 4; w++) {
            float m2 = wr[w][tid].x, s2 = wr[w][tid].y;
            float nm = fmaxf(M, m2);
            S = S * __expf(M - nm) + s2 * __expf(m2 - nm);
            M = nm;
        }
        smax[tid] = M;
        sden[tid] = 1.f / S;
    }
    __syncthreads();

    float acc[8];
#pragma unroll
    for (int k = 0; k < 8; k++) acc[k] = 0.f;
    int c0 = tid * 8;
    int hown = tid >> 4;

    for (int e0 = r0; e0 < r1; e0 += 16) {
        int mc = min(16, r1 - e0);
        if (tid < mc * 8) {
            int e = e0 + (tid >> 3);
            int h = tid & 7;
            int src = g_csr[e];
            if (h == 0) ssrc[tid >> 3] = src;
            float v = g_s1s[src * H1 + h] + sdl[h];
            v = v > 0.f ? v : SLOPE * v;
            sal[tid >> 3][h] = __expf(v - smax[h]) * sden[h];
        }
        __syncthreads();
#pragma unroll 4
        for (int j = 0; j < mc; j++) {
            int src = ssrc[j];
            float a = sal[j][hown];
            uint4 u = *(const uint4*)(g_h1h + (size_t)src * HC1 + c0);
            float2 f0 = __half22float2(*(__half2*)&u.x);
            float2 f1 = __half22float2(*(__half2*)&u.y);
            float2 f2 = __half22float2(*(__half2*)&u.z);
            float2 f3 = __half22float2(*(__half2*)&u.w);
            acc[0] = fmaf(f0.x, a, acc[0]); acc[1] = fmaf(f0.y, a, acc[1]);
            acc[2] = fmaf(f1.x, a, acc[2]); acc[3] = fmaf(f1.y, a, acc[3]);
            acc[4] = fmaf(f2.x, a, acc[4]); acc[5] = fmaf(f2.y, a, acc[5]);
            acc[6] = fmaf(f3.x, a, acc[6]); acc[7] = fmaf(f3.y, a, acc[7]);
        }
        __syncthreads();
    }

    float o[8];
#pragma unroll
    for (int k = 0; k < 8; k++) {
        float t = acc[k] + b1[c0 + k];
        o[k] = t > 0.f ? t : expm1f(t);
    }
    __half2 h0 = __floats2half2_rn(o[0], o[1]);
    __half2 h1v = __floats2half2_rn(o[2], o[3]);
    __half2 h2v = __floats2half2_rn(o[4], o[5]);
    __half2 h3 = __floats2half2_rn(o[6], o[7]);
    uint4 u;
    u.x = *(uint32_t*)&h0;
    u.y = *(uint32_t*)&h1v;
    u.z = *(uint32_t*)&h2v;
    u.w = *(uint32_t*)&h3;
    *(uint4*)(g_act1h + (size_t)n * HC1 + c0) = u;
}

// ---------------------------------------------------------------------------
// agg2: fp16 gather; writes final fp32 output
// ---------------------------------------------------------------------------
__global__ __launch_bounds__(128)
void k_agg2(const float* __restrict__ b2, float* __restrict__ out) {
    int n = blockIdx.x;
    int tid = threadIdx.x, wid = tid >> 5, lane = tid & 31;
    __shared__ float s_sd, s_m, s_d;
    __shared__ float2 wr[4];
    __shared__ float sal[64];
    __shared__ int   ssrc[64];

    if (tid == 0) s_sd = g_s2d[n];
    int r0 = g_rows[n], r1 = g_rows[n + 1];
    int deg = r1 - r0;
    __syncthreads();
    float sdv = s_sd;

    float m = -3.0e38f, s = 0.f;
    for (int i = tid; i < deg; i += 128) {
        int src = g_csr[r0 + i];
        float v = g_s2s[src] + sdv;
        v = v > 0.f ? v : SLOPE * v;
        float nm = fmaxf(m, v);
        s = s * __expf(m - nm) + __expf(v - nm);
        m = nm;
    }
#pragma unroll
    for (int o = 16; o; o >>= 1) {
        float om = __shfl_xor_sync(~0u, m, o);
        float os = __shfl_xor_sync(~0u, s, o);
        float nm = fmaxf(m, om);
        s = s * __expf(m - nm) + os * __expf(om - nm);
        m = nm;
    }
    if (!lane) wr[wid] = make_float2(m, s);
    __syncthreads();
    if (tid == 0) {
        float M = wr[0].x, S = wr[0].y;
#pragma unroll
        for (int w = 1; w < 4; w++) {
            float m2 = wr[w].x, s2 = wr[w].y;
            float nm = fmaxf(M, m2);
            S = S * __expf(M - nm) + s2 * __expf(m2 - nm);
            M = nm;
        }
        s_m = M;
        s_d = 1.f / S;
    }
    __syncthreads();
    float M = s_m, inv = s_d;

    float acc = 0.f;
    for (int e0 = r0; e0 < r1; e0 += 64) {
        int mc = min(64, r1 - e0);
        if (tid < mc) {
            int src = g_csr[e0 + tid];
            float v = g_s2s[src] + sdv;
            v = v > 0.f ? v : SLOPE * v;
            sal[tid] = __expf(v - M) * inv;
            ssrc[tid] = src;
        }
        __syncthreads();
#pragma unroll 4
        for (int j = 0; j < mc; j++) {
            float hv = __half2float(g_h2h[(size_t)ssrc[j] * C2 + tid]);
            acc = fmaf(hv, sal[j], acc);
        }
        __syncthreads();
    }
    out[(size_t)n * C2 + tid] = acc + b2[tid];
}

// ---------------------------------------------------------------------------
// launch
// ---------------------------------------------------------------------------
extern "C" void kernel_launch(void* const* d_in, const int* in_sizes, int n_in,
                              void* d_out, int out_size) {
    const float* x      = (const float*)d_in[0];
    const int*   ei     = (const int*)  d_in[1];
    const float* W1     = (const float*)d_in[2];
    const float* a_src1 = (const float*)d_in[3];
    const float* a_dst1 = (const float*)d_in[4];
    const float* b1     = (const float*)d_in[5];
    const float* W2     = (const float*)d_in[6];
    const float* a_src2 = (const float*)d_in[7];
    const float* a_dst2 = (const float*)d_in[8];
    const float* b2     = (const float*)d_in[9];
    float* out = (float*)d_out;

    int E = in_sizes[1] / 2;
    int tot = E + N_NODES;

    __half *p_xh, *p_w1t, *p_w2t, *p_h1h, *p_act1h, *p_h2h;
    float *p_s1s, *p_s1d, *p_s2s, *p_s2d;
    int* p_deg;
    cudaGetSymbolAddress((void**)&p_xh,    g_xh);
    cudaGetSymbolAddress((void**)&p_w1t,   g_w1t);
    cudaGetSymbolAddress((void**)&p_w2t,   g_w2t);
    cudaGetSymbolAddress((void**)&p_h1h,   g_h1h);
    cudaGetSymbolAddress((void**)&p_act1h, g_act1h);
    cudaGetSymbolAddress((void**)&p_h2h,   g_h2h);
    cudaGetSymbolAddress((void**)&p_s1s,   g_s1s);
    cudaGetSymbolAddress((void**)&p_s1d,   g_s1d);
    cudaGetSymbolAddress((void**)&p_s2s,   g_s2s);
    cudaGetSymbolAddress((void**)&p_s2d,   g_s2d);
    cudaGetSymbolAddress((void**)&p_deg,   g_deg);

    const int SMEM1 = 3 * (128 + 128) * 40 * 2 + 128 * 2 * 2 * 4;   // 63488
    const int SMEM2 = 4 * (64 + 64) * 40 * 2 + 64 * 2 * 2 * 4;      // 41984

    static cudaStream_t sB = nullptr;
    static cudaEvent_t evFork = nullptr, evJoin = nullptr;
    if (!sB) {
        cudaStreamCreateWithFlags(&sB, cudaStreamNonBlocking);
        cudaEventCreateWithFlags(&evFork, cudaEventDisableTiming);
        cudaEventCreateWithFlags(&evJoin, cudaEventDisableTiming);
        cudaFuncSetAttribute(k_hgemm<128, 128, 2, 2, 3>,
                             cudaFuncAttributeMaxDynamicSharedMemorySize, SMEM1);
        cudaFuncSetAttribute(k_hgemm<64, 64, 2, 2, 4>,
                             cudaFuncAttributeMaxDynamicSharedMemorySize, SMEM2);
    }

    int cb = (tot + 1023) / 1024;

    // fork: CSR chain + W2^T + s2-zeroing on stream B
    cudaEventRecord(evFork, 0);
    cudaStreamWaitEvent(sB, evFork, 0);
    cudaMemsetAsync(p_deg, 0, N_NODES * sizeof(int), sB);
    k_prep2<<<134, 256, 0, sB>>>(W2);
    k_count<<<cb, 256, 0, sB>>>(ei, E);
    k_scan<<<1, 1024, 0, sB>>>();
    k_scatter<<<cb, 256, 0, sB>>>(ei, E);
    cudaEventRecord(evJoin, sB);

    // stream A: convert + GEMM1(+score1)
    k_prep_cvt<<<921, 256>>>(x, W1);
    k_hgemm<128, 128, 2, 2, 3><<<dim3(HC1 / 128, (N_NODES + 127) / 128), 128, SMEM1>>>(
        N_NODES, HC1, F_IN, p_xh, p_w1t, p_h1h,
        p_s1s, p_s1d, a_src1, a_dst1, H1);

    // join: agg1 needs CSR + GEMM1
    cudaStreamWaitEvent(0, evJoin, 0);
    k_agg1<<<N_NODES, 128>>>(b1);

    // Layer 2
    k_hgemm<64, 64, 2, 2, 4><<<dim3(C2 / 64, (N_NODES + 63) / 64), 128, SMEM2>>>(
        N_NODES, C2, HC1, p_act1h, p_w2t, p_h2h,
        p_s2s, p_s2d, a_src2, a_dst2, 1);
    k_agg2<<<N_NODES, 128>>>(b2, out);
}

// round 17
// speedup vs baseline: 1.4795x; 1.0781x over previous
#include <cuda_runtime.h>
#include <cuda_fp16.h>
#include <cstdint>

// ---------------------------------------------------------------------------
// GAT 2-layer forward, GB300 (sm_103a)   [round-13 config + non-atomic score1]
// Stream A: prep_cvt -> GEMM1(+score1, plain store) --\
// Stream B: count -> scan -> scatter ------------------+-> agg1 -> GEMM2 -> agg2
// ---------------------------------------------------------------------------

#define N_NODES 10000
#define F_IN    256
#define H1      8
#define C1      128
#define HC1     1024
#define C2      128
#define E_BASE  160000
#define E_TOT   (E_BASE + N_NODES)
#define SLOPE   0.2f

__device__ __half g_xh[N_NODES * F_IN];
__device__ __half g_w1t[HC1 * F_IN];
__device__ __half g_w2t[C2 * HC1];
__device__ __half g_h1h[N_NODES * HC1];
__device__ __half g_act1h[N_NODES * HC1];
__device__ __half g_h2h[N_NODES * C2];
__device__ float  g_s1s[N_NODES * H1];
__device__ float  g_s1d[N_NODES * H1];
__device__ float  g_s2s[N_NODES];
__device__ float  g_s2d[N_NODES];
__device__ int    g_deg[N_NODES];
__device__ int    g_rows[N_NODES + 1];
__device__ int    g_cur[N_NODES];
__device__ int    g_csr[E_TOT + 16];

// ---------------------------------------------------------------------------
// prep_cvt: cvt_x | W1^T | W2^T | zero s2s/s2d   (stream A, 1015 blocks)
// ---------------------------------------------------------------------------
__device__ __forceinline__ void tr_cvt_tile(const float* __restrict__ W,
                                            __half* __restrict__ Wt,
                                            int K, int N, int bx, int by,
                                            float (*t)[33]) {
    int tx = threadIdx.x & 31, ty = threadIdx.x >> 5;
#pragma unroll
    for (int i = 0; i < 4; i++) {
        int row = ty + i * 8;
        t[row][tx] = W[(size_t)(by + row) * N + bx + tx];
    }
    __syncthreads();
#pragma unroll
    for (int i = 0; i < 4; i++) {
        int row = ty + i * 8;
        Wt[(size_t)(bx + row) * K + by + tx] = __float2half_rn(t[tx][row]);
    }
}

__global__ __launch_bounds__(256)
void k_prep_cvt(const float* __restrict__ x,
                const float* __restrict__ W1, const float* __restrict__ W2) {
    __shared__ float t[32][33];
    int b = blockIdx.x;
    if (b < 625) {
        int i0 = b * 1024 + threadIdx.x;
#pragma unroll
        for (int j = 0; j < 4; j++) {
            int i = i0 + j * 256;
            float4 v = ((const float4*)x)[i];
            __half2 p0 = __floats2half2_rn(v.x, v.y);
            __half2 p1 = __floats2half2_rn(v.z, v.w);
            uint2 u;
            u.x = *(uint32_t*)&p0;
            u.y = *(uint32_t*)&p1;
            ((uint2*)g_xh)[i] = u;
        }
    } else if (b < 881) {
        int bb = b - 625;
        tr_cvt_tile(W1, g_w1t, F_IN, HC1, (bb & 31) * 32, (bb >> 5) * 32, t);
    } else if (b < 1009) {
        int bb = b - 881;
        tr_cvt_tile(W2, g_w2t, HC1, C2, (bb & 3) * 32, (bb >> 2) * 32, t);
    } else {
        int bb = b - 1009;   // 0..5
        float4 z = make_float4(0.f, 0.f, 0.f, 0.f);
        if (bb < 3) {
#pragma unroll
            for (int j = 0; j < 4; j++) {
                int i = bb * 4096 + j * 1024 + threadIdx.x * 4;
                if (i < N_NODES) *(float4*)&g_s2s[i] = z;
            }
        } else {
#pragma unroll
            for (int j = 0; j < 4; j++) {
                int i = (bb - 3) * 4096 + j * 1024 + threadIdx.x * 4;
                if (i < N_NODES) *(float4*)&g_s2d[i] = z;
            }
        }
    }
}

// ---------------------------------------------------------------------------
// CSR build (stream B)
// ---------------------------------------------------------------------------
__global__ void k_count(const int* __restrict__ ei, int E) {
    int i0 = (blockIdx.x * blockDim.x + threadIdx.x) * 4;
    int tot = E + N_NODES;
#pragma unroll
    for (int j = 0; j < 4; j++) {
        int i = i0 + j;
        if (i < tot) {
            int dst = (i < E) ? ei[E + i] : (i - E);
            atomicAdd(&g_deg[dst], 1);
        }
    }
}

__global__ void k_scan() {
    __shared__ int ssum[1024];
    int tid = threadIdx.x;
    const int CH = (N_NODES + 1023) >> 10;
    int base = tid * CH;
    int s = 0;
    for (int i = 0; i < CH; i++) {
        int idx = base + i;
        if (idx < N_NODES) s += g_deg[idx];
    }
    ssum[tid] = s;
    __syncthreads();
    for (int off = 1; off < 1024; off <<= 1) {
        int v = (tid >= off) ? ssum[tid - off] : 0;
        __syncthreads();
        ssum[tid] += v;
        __syncthreads();
    }
    int run = (tid == 0) ? 0 : ssum[tid - 1];
    for (int i = 0; i < CH; i++) {
        int idx = base + i;
        if (idx < N_NODES) {
            g_rows[idx] = run;
            g_cur[idx]  = run;
            run += g_deg[idx];
        }
    }
    if (tid == 1023) g_rows[N_NODES] = ssum[1023];
}

__global__ void k_scatter(const int* __restrict__ ei, int E) {
    int i0 = (blockIdx.x * blockDim.x + threadIdx.x) * 4;
    int tot = E + N_NODES;
#pragma unroll
    for (int j = 0; j < 4; j++) {
        int i = i0 + j;
        if (i < tot) {
            int src = (i < E) ? ei[i]     : (i - E);
            int dst = (i < E) ? ei[E + i] : (i - E);
            int p = atomicAdd(&g_cur[dst], 1);
            g_csr[p] = src;
        }
    }
}

// ---------------------------------------------------------------------------
// fp16 MMA + cp.async + ldmatrix helpers
// ---------------------------------------------------------------------------
__device__ __forceinline__ void mma_f16(float* c, const uint32_t* a, const uint32_t* b) {
    asm volatile(
        "mma.sync.aligned.m16n8k16.row.col.f32.f16.f16.f32 "
        "{%0,%1,%2,%3}, {%4,%5,%6,%7}, {%8,%9}, {%0,%1,%2,%3};"
        : "+f"(c[0]), "+f"(c[1]), "+f"(c[2]), "+f"(c[3])
        : "r"(a[0]), "r"(a[1]), "r"(a[2]), "r"(a[3]), "r"(b[0]), "r"(b[1]));
}

__device__ __forceinline__ void cp16(uint32_t dst, const void* src, bool p) {
    int sz = p ? 16 : 0;
    asm volatile("cp.async.cg.shared.global [%0], [%1], 16, %2;"
                 :: "r"(dst), "l"(src), "r"(sz));
}
#define CP_COMMIT() asm volatile("cp.async.commit_group;")
#define CP_WAIT(n)  asm volatile("cp.async.wait_group %0;" :: "n"(n))

__device__ __forceinline__ void ldsm_x4(uint32_t& r0, uint32_t& r1,
                                        uint32_t& r2, uint32_t& r3, uint32_t a) {
    asm volatile("ldmatrix.sync.aligned.m8n8.x4.shared.b16 {%0,%1,%2,%3}, [%4];"
                 : "=r"(r0), "=r"(r1), "=r"(r2), "=r"(r3) : "r"(a));
}
__device__ __forceinline__ void ldsm_x2(uint32_t& r0, uint32_t& r1, uint32_t a) {
    asm volatile("ldmatrix.sync.aligned.m8n8.x2.shared.b16 {%0,%1}, [%2];"
                 : "=r"(r0), "=r"(r1) : "r"(a));
}

// ---------------------------------------------------------------------------
// GEMM: C[M,Ng] = A[M,K] @ Bt[Ng,K]^T, fp16 in/out, fp32 accum.
// STAGES-deep cp.async pipeline, one __syncthreads per BK-iter, ldmatrix.
// Score epilogue: ATOMIC ? atomicAdd (split-N) : plain store (BN covers head).
// ---------------------------------------------------------------------------
template<int BM, int BN, int WARPS_M, int WARPS_N, int STAGES, bool ATOMIC>
__global__ __launch_bounds__(32 * WARPS_M * WARPS_N)
void k_hgemm(int M, int Ng, int K,
             const __half* __restrict__ A, const __half* __restrict__ Bt,
             __half* __restrict__ Ch,
             float* __restrict__ ss, float* __restrict__ sd,
             const float* __restrict__ a_src, const float* __restrict__ a_dst,
             int HS) {
    constexpr int BK = 32;
    constexpr int SA = BK + 8;
    constexpr int NTHR = 32 * WARPS_M * WARPS_N;
    constexpr int WM = BM / WARPS_M, WN = BN / WARPS_N;
    constexpr int MT = WM / 16, NT = WN / 8;
    constexpr int RPR = NTHR / 4;
    constexpr int AROUND = BM / RPR, BROUND = BN / RPR;

    extern __shared__ __align__(16) char smem_raw[];
    __half* AsBase = (__half*)smem_raw;
    __half* BsBase = AsBase + STAGES * BM * SA;
    float* s_red = (float*)(BsBase + STAGES * BN * SA);

    int tid = threadIdx.x, wid = tid >> 5, lane = tid & 31;
    int bm0 = blockIdx.y * BM, bn0 = blockIdx.x * BN;
    int wm_idx = wid / WARPS_N, wn_idx = wid % WARPS_N;
    int wm = wm_idx * WM, wn = wn_idx * WN;
    int head = (bn0 >> 7);

    float acc[MT][NT][4];
#pragma unroll
    for (int i = 0; i < MT; i++)
#pragma unroll
        for (int j = 0; j < NT; j++)
#pragma unroll
            for (int l = 0; l < 4; l++) acc[i][j][l] = 0.f;

    int ld_row = tid >> 2;
    int ld_ch  = (tid & 3) * 8;

    uint32_t as_sh = (uint32_t)__cvta_generic_to_shared(AsBase);
    uint32_t bs_sh = (uint32_t)__cvta_generic_to_shared(BsBase);
    int a_lrow = wm + (lane & 15);
    int a_lcol = (lane & 16) ? 8 : 0;
    int b_lrow = wn + (lane & 7);
    int b_lcol = (lane & 8) ? 8 : 0;

    auto cp_tile = [&](int buf, int k0) {
        __half* As = AsBase + buf * BM * SA;
        __half* Bs = BsBase + buf * BN * SA;
#pragma unroll
        for (int i = 0; i < AROUND; i++) {
            int rl = ld_row + i * RPR;
            int gr = bm0 + rl;
            uint32_t dst = (uint32_t)__cvta_generic_to_shared(&As[rl * SA + ld_ch]);
            cp16(dst, A + (size_t)gr * K + k0 + ld_ch, gr < M);
        }
#pragma unroll
        for (int i = 0; i < BROUND; i++) {
            int nl = ld_row + i * RPR;
            uint32_t dst = (uint32_t)__cvta_generic_to_shared(&Bs[nl * SA + ld_ch]);
            cp16(dst, Bt + (size_t)(bn0 + nl) * K + k0 + ld_ch, true);
        }
        CP_COMMIT();
    };

    auto compute = [&](int buf) {
        uint32_t as0 = as_sh + (uint32_t)(buf * BM * SA) * 2;
        uint32_t bs0 = bs_sh + (uint32_t)(buf * BN * SA) * 2;
#pragma unroll
        for (int ks = 0; ks < 2; ks++) {
            uint32_t af[MT][4], bf[NT][2];
#pragma unroll
            for (int mt = 0; mt < MT; mt++) {
                uint32_t addr = as0 + ((a_lrow + mt * 16) * SA + ks * 16 + a_lcol) * 2;
                ldsm_x4(af[mt][0], af[mt][1], af[mt][2], af[mt][3], addr);
            }
#pragma unroll
            for (int nt = 0; nt < NT; nt++) {
                uint32_t addr = bs0 + ((b_lrow + nt * 8) * SA + ks * 16 + b_lcol) * 2;
                ldsm_x2(bf[nt][0], bf[nt][1], addr);
            }
#pragma unroll
            for (int mt = 0; mt < MT; mt++)
#pragma unroll
                for (int nt = 0; nt < NT; nt++)
                    mma_f16(acc[mt][nt], af[mt], bf[nt]);
        }
    };

    int iters = K / BK;
    for (int s = 0; s < STAGES - 1 && s < iters; s++) cp_tile(s, s * BK);
    for (int it = 0; it < iters; it++) {
        int rem = iters - 1 - it;
        if (rem >= STAGES - 2) { CP_WAIT(STAGES - 2); }
        else if (STAGES > 3 && rem == 1) { CP_WAIT(1); }
        else { CP_WAIT(0); }
        __syncthreads();
        compute(it % STAGES);
        if (it + STAGES - 1 < iters)
            cp_tile((it + STAGES - 1) % STAGES, (it + STAGES - 1) * BK);
    }

    // ---- epilogue: fp16 store + fused score partials ----
    float ps[MT][2], pd[MT][2];
#pragma unroll
    for (int mt = 0; mt < MT; mt++) {
        ps[mt][0] = ps[mt][1] = 0.f;
        pd[mt][0] = pd[mt][1] = 0.f;
    }
#pragma unroll
    for (int nt = 0; nt < NT; nt++) {
        int cl = wn + nt * 8 + (lane & 3) * 2;
        float a0s = a_src[bn0 + cl], a1s = a_src[bn0 + cl + 1];
        float a0d = a_dst[bn0 + cl], a1d = a_dst[bn0 + cl + 1];
#pragma unroll
        for (int mt = 0; mt < MT; mt++) {
            int r = bm0 + wm + mt * 16 + (lane >> 2);
            int c = bn0 + cl;
            if (r < M)
                *(__half2*)(Ch + (size_t)r * Ng + c) =
                    __floats2half2_rn(acc[mt][nt][0], acc[mt][nt][1]);
            if (r + 8 < M)
                *(__half2*)(Ch + (size_t)(r + 8) * Ng + c) =
                    __floats2half2_rn(acc[mt][nt][2], acc[mt][nt][3]);
            ps[mt][0] = fmaf(acc[mt][nt][0], a0s, fmaf(acc[mt][nt][1], a1s, ps[mt][0]));
            ps[mt][1] = fmaf(acc[mt][nt][2], a0s, fmaf(acc[mt][nt][3], a1s, ps[mt][1]));
            pd[mt][0] = fmaf(acc[mt][nt][0], a0d, fmaf(acc[mt][nt][1], a1d, pd[mt][0]));
            pd[mt][1] = fmaf(acc[mt][nt][2], a0d, fmaf(acc[mt][nt][3], a1d, pd[mt][1]));
        }
    }
#pragma unroll
    for (int o = 1; o <= 2; o <<= 1) {
#pragma unroll
        for (int mt = 0; mt < MT; mt++) {
            ps[mt][0] += __shfl_xor_sync(~0u, ps[mt][0], o);
            ps[mt][1] += __shfl_xor_sync(~0u, ps[mt][1], o);
            pd[mt][0] += __shfl_xor_sync(~0u, pd[mt][0], o);
            pd[mt][1] += __shfl_xor_sync(~0u, pd[mt][1], o);
        }
    }
    if ((lane & 3) == 0) {
#pragma unroll
        for (int mt = 0; mt < MT; mt++) {
            int row = wm + mt * 16 + (lane >> 2);
            s_red[(row * WARPS_N + wn_idx) * 2 + 0] = ps[mt][0];
            s_red[(row * WARPS_N + wn_idx) * 2 + 1] = pd[mt][0];
            s_red[((row + 8) * WARPS_N + wn_idx) * 2 + 0] = ps[mt][1];
            s_red[((row + 8) * WARPS_N + wn_idx) * 2 + 1] = pd[mt][1];
        }
    }
    __syncthreads();
    if (tid < BM) {
        int r = bm0 + tid;
        if (r < M) {
            float s = 0.f, d = 0.f;
#pragma unroll
            for (int w = 0; w < WARPS_N; w++) {
                s += s_red[(tid * WARPS_N + w) * 2 + 0];
                d += s_red[(tid * WARPS_N + w) * 2 + 1];
            }
            if (ATOMIC) {
                atomicAdd(&ss[(size_t)r * HS + head], s);
                atomicAdd(&sd[(size_t)r * HS + head], d);
            } else {
                ss[(size_t)r * HS + head] = s;
                sd[(size_t)r * HS + head] = d;
            }
        }
    }
}

// ---------------------------------------------------------------------------
// agg1: one block (128 thr) per dst node; online softmax; fp16 gather;
// writes fp16 act1 (+b1, ELU).
// ---------------------------------------------------------------------------
__global__ __launch_bounds__(128)
void k_agg1(const float* __restrict__ b1) {
    int n = blockIdx.x;
    int tid = threadIdx.x, wid = tid >> 5, lane = tid & 31;
    __shared__ float  sdl[8], smax[8], sden[8];
    __shared__ float2 wr[4][8];
    __shared__ float  sal[16][8];
    __shared__ int    ssrc[16];

    if (tid < 8) sdl[tid] = g_s1d[n * H1 + tid];
    int r0 = g_rows[n], r1 = g_rows[n + 1];
    int deg = r1 - r0;
    __syncthreads();

    int myh = tid & 7;
    float sdh = sdl[myh];

    float m = -3.0e38f, s = 0.f;
    for (int idx = tid; idx < deg * 8; idx += 128) {
        int src = g_csr[r0 + (idx >> 3)];
        float v = g_s1s[src * H1 + myh] + sdh;
        v = v > 0.f ? v : SLOPE * v;
        float nm = fmaxf(m, v);
        s = s * __expf(m - nm) + __expf(v - nm);
        m = nm;
    }
#pragma unroll
    for (int o = 8; o <= 16; o <<= 1) {
        float om = __shfl_xor_sync(~0u, m, o);
        float os = __shfl_xor_sync(~0u, s, o);
        float nm = fmaxf(m, om);
        s = s * __expf(m - nm) + os * __expf(om - nm);
        m = nm;
    }
    if (lane < 8) wr[wid][lane] = make_float2(m, s);
    __syncthreads();
    if (tid < 8) {
        float M = wr[0][tid].x, S = wr[0][tid].y;
#pragma unroll
        for (int w = 1; w < 4; w++) {
            float m2 = wr[w][tid].x, s2 = wr[w][tid].y;
            float nm = fmaxf(M, m2);
            S = S * __expf(M - nm) + s2 * __expf(m2 - nm);
            M = nm;
        }
        smax[tid] = M;
        sden[tid] = 1.f / S;
    }
    __syncthreads();

    float acc[8];
#pragma unroll
    for (int k = 0; k < 8; k++) acc[k] = 0.f;
    int c0 = tid * 8;
    int hown = tid >> 4;

    for (int e0 = r0; e0 < r1; e0 += 16) {
        int mc = min(16, r1 - e0);
        if (tid < mc * 8) {
            int e = e0 + (tid >> 3);
            int h = tid & 7;
            int src = g_csr[e];
            if (h == 0) ssrc[tid >> 3] = src;
            float v = g_s1s[src * H1 + h] + sdl[h];
            v = v > 0.f ? v : SLOPE * v;
            sal[tid >> 3][h] = __expf(v - smax[h]) * sden[h];
        }
        __syncthreads();
#pragma unroll 4
        for (int j = 0; j < mc; j++) {
            int src = ssrc[j];
            float a = sal[j][hown];
            uint4 u = *(const uint4*)(g_h1h + (size_t)src * HC1 + c0);
            float2 f0 = __half22float2(*(__half2*)&u.x);
            float2 f1 = __half22float2(*(__half2*)&u.y);
            float2 f2 = __half22float2(*(__half2*)&u.z);
            float2 f3 = __half22float2(*(__half2*)&u.w);
            acc[0] = fmaf(f0.x, a, acc[0]); acc[1] = fmaf(f0.y, a, acc[1]);
            acc[2] = fmaf(f1.x, a, acc[2]); acc[3] = fmaf(f1.y, a, acc[3]);
            acc[4] = fmaf(f2.x, a, acc[4]); acc[5] = fmaf(f2.y, a, acc[5]);
            acc[6] = fmaf(f3.x, a, acc[6]); acc[7] = fmaf(f3.y, a, acc[7]);
        }
        __syncthreads();
    }

    float o[8];
#pragma unroll
    for (int k = 0; k < 8; k++) {
        float t = acc[k] + b1[c0 + k];
        o[k] = t > 0.f ? t : expm1f(t);
    }
    __half2 h0 = __floats2half2_rn(o[0], o[1]);
    __half2 h1v = __floats2half2_rn(o[2], o[3]);
    __half2 h2v = __floats2half2_rn(o[4], o[5]);
    __half2 h3 = __floats2half2_rn(o[6], o[7]);
    uint4 u;
    u.x = *(uint32_t*)&h0;
    u.y = *(uint32_t*)&h1v;
    u.z = *(uint32_t*)&h2v;
    u.w = *(uint32_t*)&h3;
    *(uint4*)(g_act1h + (size_t)n * HC1 + c0) = u;
}

// ---------------------------------------------------------------------------
// agg2: fp16 gather; writes final fp32 output
// ---------------------------------------------------------------------------
__global__ __launch_bounds__(128)
void k_agg2(const float* __restrict__ b2, float* __restrict__ out) {
    int n = blockIdx.x;
    int tid = threadIdx.x, wid = tid >> 5, lane = tid & 31;
    __shared__ float s_sd, s_m, s_d;
    __shared__ float2 wr[4];
    __shared__ float sal[64];
    __shared__ int   ssrc[64];

    if (tid == 0) s_sd = g_s2d[n];
    int r0 = g_rows[n], r1 = g_rows[n + 1];
    int deg = r1 - r0;
    __syncthreads();
    float sdv = s_sd;

    float m = -3.0e38f, s = 0.f;
    for (int i = tid; i < deg; i += 128) {
        int src = g_csr[r0 + i];
        float v = g_s2s[src] + sdv;
        v = v > 0.f ? v : SLOPE * v;
        float nm = fmaxf(m, v);
        s = s * __expf(m - nm) + __expf(v - nm);
        m = nm;
    }
#pragma unroll
    for (int o = 16; o; o >>= 1) {
        float om = __shfl_xor_sync(~0u, m, o);
        float os = __shfl_xor_sync(~0u, s, o);
        float nm = fmaxf(m, om);
        s = s * __expf(m - nm) + os * __expf(om - nm);
        m = nm;
    }
    if (!lane) wr[wid] = make_float2(m, s);
    __syncthreads();
    if (tid == 0) {
        float M = wr[0].x, S = wr[0].y;
#pragma unroll
        for (int w = 1; w < 4; w++) {
            float m2 = wr[w].x, s2 = wr[w].y;
            float nm = fmaxf(M, m2);
            S = S * __expf(M - nm) + s2 * __expf(m2 - nm);
            M = nm;
        }
        s_m = M;
        s_d = 1.f / S;
    }
    __syncthreads();
    float M = s_m, inv = s_d;

    float acc = 0.f;
    for (int e0 = r0; e0 < r1; e0 += 64) {
        int mc = min(64, r1 - e0);
        if (tid < mc) {
            int src = g_csr[e0 + tid];
            float v = g_s2s[src] + sdv;
            v = v > 0.f ? v : SLOPE * v;
            sal[tid] = __expf(v - M) * inv;
            ssrc[tid] = src;
        }
        __syncthreads();
#pragma unroll 4
        for (int j = 0; j < mc; j++) {
            float hv = __half2float(g_h2h[(size_t)ssrc[j] * C2 + tid]);
            acc = fmaf(hv, sal[j], acc);
        }
        __syncthreads();
    }
    out[(size_t)n * C2 + tid] = acc + b2[tid];
}

// ---------------------------------------------------------------------------
// launch
// ---------------------------------------------------------------------------
extern "C" void kernel_launch(void* const* d_in, const int* in_sizes, int n_in,
                              void* d_out, int out_size) {
    const float* x      = (const float*)d_in[0];
    const int*   ei     = (const int*)  d_in[1];
    const float* W1     = (const float*)d_in[2];
    const float* a_src1 = (const float*)d_in[3];
    const float* a_dst1 = (const float*)d_in[4];
    const float* b1     = (const float*)d_in[5];
    const float* W2     = (const float*)d_in[6];
    const float* a_src2 = (const float*)d_in[7];
    const float* a_dst2 = (const float*)d_in[8];
    const float* b2     = (const float*)d_in[9];
    float* out = (float*)d_out;

    int E = in_sizes[1] / 2;
    int tot = E + N_NODES;

    __half *p_xh, *p_w1t, *p_w2t, *p_h1h, *p_act1h, *p_h2h;
    float *p_s1s, *p_s1d, *p_s2s, *p_s2d;
    int* p_deg;
    cudaGetSymbolAddress((void**)&p_xh,    g_xh);
    cudaGetSymbolAddress((void**)&p_w1t,   g_w1t);
    cudaGetSymbolAddress((void**)&p_w2t,   g_w2t);
    cudaGetSymbolAddress((void**)&p_h1h,   g_h1h);
    cudaGetSymbolAddress((void**)&p_act1h, g_act1h);
    cudaGetSymbolAddress((void**)&p_h2h,   g_h2h);
    cudaGetSymbolAddress((void**)&p_s1s,   g_s1s);
    cudaGetSymbolAddress((void**)&p_s1d,   g_s1d);
    cudaGetSymbolAddress((void**)&p_s2s,   g_s2s);
    cudaGetSymbolAddress((void**)&p_s2d,   g_s2d);
    cudaGetSymbolAddress((void**)&p_deg,   g_deg);

    const int SMEM1 = 3 * (128 + 128) * 40 * 2 + 128 * 2 * 2 * 4;   // 63488
    const int SMEM2 = 4 * (64 + 64) * 40 * 2 + 64 * 2 * 2 * 4;      // 41984

    static cudaStream_t sB = nullptr;
    static cudaEvent_t evFork = nullptr, evJoin = nullptr;
    if (!sB) {
        cudaStreamCreateWithFlags(&sB, cudaStreamNonBlocking);
        cudaEventCreateWithFlags(&evFork, cudaEventDisableTiming);
        cudaEventCreateWithFlags(&evJoin, cudaEventDisableTiming);
        cudaFuncSetAttribute(k_hgemm<128, 128, 2, 2, 3, false>,
                             cudaFuncAttributeMaxDynamicSharedMemorySize, SMEM1);
        cudaFuncSetAttribute(k_hgemm<64, 64, 2, 2, 4, true>,
                             cudaFuncAttributeMaxDynamicSharedMemorySize, SMEM2);
    }

    int cb = (tot + 1023) / 1024;

    // fork: CSR chain on stream B (only CSR work — round-13 arrangement)
    cudaEventRecord(evFork, 0);
    cudaStreamWaitEvent(sB, evFork, 0);
    cudaMemsetAsync(p_deg, 0, N_NODES * sizeof(int), sB);
    k_count<<<cb, 256, 0, sB>>>(ei, E);
    k_scan<<<1, 1024, 0, sB>>>();
    k_scatter<<<cb, 256, 0, sB>>>(ei, E);
    cudaEventRecord(evJoin, sB);

    // stream A: convert + GEMM1(+score1, non-atomic)
    k_prep_cvt<<<1015, 256>>>(x, W1, W2);
    k_hgemm<128, 128, 2, 2, 3, false><<<dim3(HC1 / 128, (N_NODES + 127) / 128), 128, SMEM1>>>(
        N_NODES, HC1, F_IN, p_xh, p_w1t, p_h1h,
        p_s1s, p_s1d, a_src1, a_dst1, H1);

    // join: agg1 needs CSR + GEMM1
    cudaStreamWaitEvent(0, evJoin, 0);
    k_agg1<<<N_NODES, 128>>>(b1);

    // Layer 2 (split-N -> atomic scores)
    k_hgemm<64, 64, 2, 2, 4, true><<<dim3(C2 / 64, (N_NODES + 63) / 64), 128, SMEM2>>>(
        N_NODES, C2, HC1, p_act1h, p_w2t, p_h2h,
        p_s2s, p_s2d, a_src2, a_dst2, 1);
    k_agg2<<<N_NODES, 128>>>(b2, out);
}